// round 15
// baseline (speedup 1.0000x reference)
#include <cuda_runtime.h>
#include <cuda_fp16.h>

#define NB   16
#define CHN  512
#define NSP  1024

// Scratch (__device__ globals — allocation-rule safe). Pure fp16.
__device__ __half g_hT[(size_t)NB * NSP * CHN];         // groupnorm out, [B,N,C]
__device__ __half g_qkT[(size_t)NB * NSP * 2 * CHN];    // q|k, [B,N,2C]
__device__ __half g_v[(size_t)NB * CHN * NSP];          // v, [B,C,N]
__device__ float  g_attn[(size_t)NB * NSP * NSP];       // scores fp32
__device__ __half g_attn_h[(size_t)NB * NSP * NSP];     // probs fp16
__device__ __half g_oT[(size_t)NB * NSP * CHN];         // attn@v, [B,N,C]
__device__ __half g_wqkv[3 * CHN * CHN];
__device__ __half g_wp[CHN * CHN];

// ---------------- helpers ----------------
__device__ __forceinline__ unsigned smem_u32(const void* p) {
    unsigned a;
    asm("{ .reg .u64 t; cvta.to.shared.u64 t, %1; cvt.u32.u64 %0, t; }"
        : "=r"(a) : "l"(p));
    return a;
}
__device__ __forceinline__ void ldsm4(unsigned r[4], unsigned addr) {
    asm volatile("ldmatrix.sync.aligned.m8n8.x4.shared.b16 {%0,%1,%2,%3}, [%4];"
                 : "=r"(r[0]), "=r"(r[1]), "=r"(r[2]), "=r"(r[3]) : "r"(addr));
}
__device__ __forceinline__ void mma16816(float c[4], const unsigned a[4], const unsigned b[2]) {
    asm volatile(
        "mma.sync.aligned.m16n8k16.row.col.f32.f16.f16.f32 "
        "{%0,%1,%2,%3}, {%4,%5,%6,%7}, {%8,%9}, {%0,%1,%2,%3};"
        : "+f"(c[0]), "+f"(c[1]), "+f"(c[2]), "+f"(c[3])
        : "r"(a[0]), "r"(a[1]), "r"(a[2]), "r"(a[3]), "r"(b[0]), "r"(b[1]));
}
__device__ __forceinline__ void cpa16(unsigned dst, const void* src) {
    asm volatile("cp.async.cg.shared.global [%0], [%1], 16;" :: "r"(dst), "l"(src));
}
#define CPA_COMMIT() asm volatile("cp.async.commit_group;" ::: "memory")
#define CPA_WAIT(n)  asm volatile("cp.async.wait_group %0;" :: "n"(n) : "memory")

// ---------------------------------------------------------------------------
// GEMM body: D[m,n] = sum_k A[m,k]*B[n,k] (K-major), fp16 -> fp32 accum.
// Block tile 128x128, KC=64, 2-stage cp.async, 2 CTAs/SM. Warp tile 64x32.
// Hoisted ldsm4 batches per ks-step, 16-MMA bursts.
// EPI: 0 QK(+bias[n], fp16) | 1 V(+bias[m], fp16) | 2 SCORE(*alpha, f32)
//      3 AV(fp16) | 4 PROJ(+bias[m]+resid, f32)
// ---------------------------------------------------------------------------
#define MT 128
#define NT 128
#define KC 64
#define PITCH 144                // 128B row + 16B pad; conflict-free ldsm phases
#define TILE_B (128 * PITCH)     // 18432
#define OFF_A  0
#define OFF_B  TILE_B
#define STAGE  (2 * TILE_B)      // 36864
#define SMEM_BYTES (2 * STAGE)   // 73728 -> 2 CTAs/SM

template <int EPI>
__device__ __forceinline__ void gemm_body(
    int bx, int by, int bz, char* smem,
    const __half* __restrict__ Ah, int lda, long long sA,
    const __half* __restrict__ Bh, int ldb, long long sB, int K,
    float* __restrict__ Cf, __half* __restrict__ Ch,
    int ldc, long long sC,
    const float* __restrict__ bias,
    const float* __restrict__ resid, long long sR, float alpha) {
    const unsigned sb = smem_u32(smem);
    const int tid = threadIdx.x, lane = tid & 31, wid = tid >> 5;
    const int m0 = by * MT, n0 = bx * NT;
    const int wm0 = (wid >> 2) * 64, wn0 = (wid & 3) * 32;

    // fill mapping: row = tid>>1, 64B segment (tid&1) — 128 rows x 128B
    const int grow = tid >> 1;
    const int gsegB = (tid & 1) * 64;

    const char* pA = (const char*)(Ah + (size_t)bz * sA + (size_t)(m0 + grow) * lda) + gsegB;
    const char* pB = (const char*)(Bh + (size_t)bz * sB + (size_t)(n0 + grow) * ldb) + gsegB;
    const unsigned drow = (unsigned)(grow * PITCH + gsegB);

    const unsigned aLane = (unsigned)((wm0 + (lane & 15)) * PITCH + ((lane >> 4) & 1) * 16);
    const unsigned bLane = (unsigned)((wn0 + (lane & 7) + ((lane >> 4) & 1) * 8) * PITCH
                                      + ((lane >> 3) & 1) * 16);

    auto fill = [&](int c) {
        const unsigned d = sb + (unsigned)((c & 1) * STAGE) + drow;
        const size_t kb = (size_t)c * (KC * 2);
        cpa16(d + OFF_A,      pA + kb);      cpa16(d + OFF_A + 16, pA + kb + 16);
        cpa16(d + OFF_A + 32, pA + kb + 32); cpa16(d + OFF_A + 48, pA + kb + 48);
        cpa16(d + OFF_B,      pB + kb);      cpa16(d + OFF_B + 16, pB + kb + 16);
        cpa16(d + OFF_B + 32, pB + kb + 32); cpa16(d + OFF_B + 48, pB + kb + 48);
        CPA_COMMIT();
    };

    const int nch = K / KC;
    fill(0);

    float acc[4][4][4] = {};

    for (int c = 0; c < nch; c++) {
        CPA_WAIT(0);
        __syncthreads();
        if (c + 1 < nch) fill(c + 1);

        const unsigned sbuf = sb + (unsigned)((c & 1) * STAGE);
#pragma unroll
        for (int ks = 0; ks < 4; ks++) {
            unsigned bf[4][2];
            {
                unsigned t[4];
                ldsm4(t, sbuf + OFF_B + bLane + ks * 32);
                bf[0][0] = t[0]; bf[0][1] = t[1];
                bf[1][0] = t[2]; bf[1][1] = t[3];
                ldsm4(t, sbuf + OFF_B + bLane + 16 * PITCH + ks * 32);
                bf[2][0] = t[0]; bf[2][1] = t[1];
                bf[3][0] = t[2]; bf[3][1] = t[3];
            }
            unsigned af[4][4];
#pragma unroll
            for (int am = 0; am < 4; am++)
                ldsm4(af[am], sbuf + OFF_A + aLane + am * (16 * PITCH) + ks * 32);
#pragma unroll
            for (int am = 0; am < 4; am++)
#pragma unroll
                for (int an = 0; an < 4; an++)
                    mma16816(acc[am][an], af[am], bf[an]);
        }
    }

    // ---- epilogue ----
    const int r0 = m0 + wm0 + (lane >> 2);
    const int c0 = n0 + wn0 + (lane & 3) * 2;
#pragma unroll
    for (int am = 0; am < 4; am++) {
#pragma unroll
        for (int an = 0; an < 4; an++) {
            float f0 = acc[am][an][0], f1 = acc[am][an][1];
            float f2 = acc[am][an][2], f3 = acc[am][an][3];
            const int r = r0 + am * 16;
            const int cc = c0 + an * 8;
            if (EPI == 2) { f0 *= alpha; f1 *= alpha; f2 *= alpha; f3 *= alpha; }
            if (EPI == 0) {
                float b0 = bias[cc], b1 = bias[cc + 1];
                f0 += b0; f1 += b1; f2 += b0; f3 += b1;
            }
            if (EPI == 1 || EPI == 4) {
                float ba = bias[r], bb = bias[r + 8];
                f0 += ba; f1 += ba; f2 += bb; f3 += bb;
            }
            const size_t o0 = (size_t)bz * sC + (size_t)r * ldc + cc;
            const size_t o1 = o0 + (size_t)8 * ldc;
            if (EPI == 4) {
                const float* rp = resid + (size_t)bz * sR + (size_t)r * ldc + cc;
                float2 rv0 = *(const float2*)rp;
                float2 rv1 = *(const float2*)(rp + (size_t)8 * ldc);
                f0 += rv0.x; f1 += rv0.y; f2 += rv1.x; f3 += rv1.y;
            }
            if (EPI == 2 || EPI == 4) {
                *(float2*)(Cf + o0) = make_float2(f0, f1);
                *(float2*)(Cf + o1) = make_float2(f2, f3);
            } else {
                union { __half b[2]; unsigned u; } H0, H1;
                H0.b[0] = __float2half_rn(f0); H0.b[1] = __float2half_rn(f1);
                H1.b[0] = __float2half_rn(f2); H1.b[1] = __float2half_rn(f3);
                *(unsigned*)(Ch + o0) = H0.u;
                *(unsigned*)(Ch + o1) = H1.u;
            }
        }
    }
}

template <int EPI>
__global__ void __launch_bounds__(256, 2) mma_gemm(
    const __half* __restrict__ Ah, int lda, long long sA,
    const __half* __restrict__ Bh, int ldb, long long sB, int K,
    float* __restrict__ Cf, __half* __restrict__ Ch,
    int ldc, long long sC,
    const float* __restrict__ bias,
    const float* __restrict__ resid, long long sR, float alpha) {
    extern __shared__ char smem[];
    gemm_body<EPI>(blockIdx.x, blockIdx.y, blockIdx.z, smem,
                   Ah, lda, sA, Bh, ldb, sB, K, Cf, Ch, ldc, sC,
                   bias, resid, sR, alpha);
}

// Combined QK + V kernel — both depend only on hT; one launch fills waves better.
// grid (8, 12, 16): y<8 -> QK tile (M=1024), y>=8 -> V tile (M=512).
__global__ void __launch_bounds__(256, 2) qkv_combo(
    const __half* __restrict__ hT, const __half* __restrict__ wq,
    __half* __restrict__ qkT, __half* __restrict__ v,
    const float* __restrict__ qkvb) {
    extern __shared__ char smem[];
    const long long sHT = (long long)NSP * CHN;
    const long long sQK = (long long)NSP * 1024;
    const long long sV  = (long long)CHN * NSP;
    if (blockIdx.y < 8) {
        // qkT[n, o] = sum_c hT[n,c] * Wqk[o,c] + qkv_b[o]
        gemm_body<0>(blockIdx.x, blockIdx.y, blockIdx.z, smem,
                     hT, CHN, sHT, wq, CHN, 0LL, CHN,
                     nullptr, qkT, 1024, sQK, qkvb, nullptr, 0LL, 1.f);
    } else {
        // v[c, n] = sum_k Wv[c,k] * hT[n,k] + qkv_b[1024+c]
        gemm_body<1>(blockIdx.x, blockIdx.y - 8, blockIdx.z, smem,
                     wq + 1024 * CHN, CHN, 0LL, hT, CHN, sHT, CHN,
                     nullptr, v, NSP, sV, qkvb + 1024, nullptr, 0LL, 1.f);
    }
}

// ---------------------------------------------------------------------------
// GroupNorm -> transposed fp16 output hT[B, N, C]
// ---------------------------------------------------------------------------
__global__ void __launch_bounds__(256) groupnorm_t(const float* __restrict__ x,
                                                   const float* __restrict__ gw,
                                                   const float* __restrict__ gb,
                                                   __half* __restrict__ hh) {
    const int b = blockIdx.x >> 3, g = blockIdx.x & 7;
    const float* xp = x + ((size_t)b * CHN + (size_t)g * 64) * NSP;

    float s = 0.f, ss = 0.f;
    for (int i = threadIdx.x * 4; i < 64 * NSP; i += 1024) {
        float4 v = *(const float4*)(xp + i);
        s += v.x + v.y + v.z + v.w;
        ss += v.x * v.x + v.y * v.y + v.z * v.z + v.w * v.w;
    }
    __shared__ float sa[8], sb2[8];
    for (int o = 16; o > 0; o >>= 1) {
        s += __shfl_xor_sync(0xffffffffu, s, o);
        ss += __shfl_xor_sync(0xffffffffu, ss, o);
    }
    if ((threadIdx.x & 31) == 0) { sa[threadIdx.x >> 5] = s; sb2[threadIdx.x >> 5] = ss; }
    __syncthreads();
    s = 0.f; ss = 0.f;
#pragma unroll
    for (int i = 0; i < 8; i++) { s += sa[i]; ss += sb2[i]; }
    const float inv_n = 1.f / (64.f * (float)NSP);
    const float mean = s * inv_n;
    const float rstd = rsqrtf(ss * inv_n - mean * mean + 1e-5f);

    const int ci_w = threadIdx.x & 63;
    const int cg = g * 64 + ci_w;
    const float sc = gw[cg] * rstd;
    const float bi = gb[cg] - mean * sc;

    __shared__ float tile[64][65];
    const int ci_r = threadIdx.x >> 2;
    const int nj = (threadIdx.x & 3) * 16;
    const int nbase = (threadIdx.x >> 6) * 16;

    for (int tt = 0; tt < 16; tt++) {
        const int n0 = tt * 64;
        __syncthreads();
        const float* src = xp + (size_t)ci_r * NSP + n0 + nj;
#pragma unroll
        for (int q = 0; q < 4; q++) {
            float4 v = *(const float4*)(src + q * 4);
            tile[ci_r][nj + q*4 + 0] = v.x; tile[ci_r][nj + q*4 + 1] = v.y;
            tile[ci_r][nj + q*4 + 2] = v.z; tile[ci_r][nj + q*4 + 3] = v.w;
        }
        __syncthreads();
#pragma unroll
        for (int k = 0; k < 16; k++) {
            const int nl = nbase + k;
            float y = tile[ci_w][nl] * sc + bi;
            hh[((size_t)b * NSP + n0 + nl) * CHN + cg] = __float2half_rn(y);
        }
    }
}

// ---------------------------------------------------------------------------
// Softmax (fp32 in) -> fp16 probs
// ---------------------------------------------------------------------------
__global__ void __launch_bounds__(256) softmax_h(const float* __restrict__ a,
                                                 __half* __restrict__ oh) {
    __shared__ float red[8];
    const float* row = a + (size_t)blockIdx.x * NSP;
    float4 v = ((const float4*)row)[threadIdx.x];

    float m = fmaxf(fmaxf(v.x, v.y), fmaxf(v.z, v.w));
    for (int o = 16; o > 0; o >>= 1) m = fmaxf(m, __shfl_xor_sync(0xffffffffu, m, o));
    int w = threadIdx.x >> 5;
    if ((threadIdx.x & 31) == 0) red[w] = m;
    __syncthreads();
    m = red[0];
#pragma unroll
    for (int i = 1; i < 8; i++) m = fmaxf(m, red[i]);

    v.x = __expf(v.x - m); v.y = __expf(v.y - m);
    v.z = __expf(v.z - m); v.w = __expf(v.w - m);
    float su = v.x + v.y + v.z + v.w;
    for (int o = 16; o > 0; o >>= 1) su += __shfl_xor_sync(0xffffffffu, su, o);
    __syncthreads();
    if ((threadIdx.x & 31) == 0) red[w] = su;
    __syncthreads();
    su = red[0] + red[1] + red[2] + red[3] + red[4] + red[5] + red[6] + red[7];
    float inv = 1.0f / su;

    union { __half b[4]; uint2 u; } P;
    P.b[0] = __float2half_rn(v.x * inv);
    P.b[1] = __float2half_rn(v.y * inv);
    P.b[2] = __float2half_rn(v.z * inv);
    P.b[3] = __float2half_rn(v.w * inv);
    *(uint2*)(oh + (size_t)blockIdx.x * NSP + threadIdx.x * 4) = P.u;
}

// fp32 -> fp16
__global__ void cast_h(const float* __restrict__ s, __half* __restrict__ h, int n) {
    int i = (blockIdx.x * blockDim.x + threadIdx.x) * 4;
    if (i < n) {
        float4 v = *(const float4*)(s + i);
        union { __half b[4]; uint2 u; } P;
        P.b[0] = __float2half_rn(v.x); P.b[1] = __float2half_rn(v.y);
        P.b[2] = __float2half_rn(v.z); P.b[3] = __float2half_rn(v.w);
        *(uint2*)(h + i) = P.u;
    }
}

// ---------------------------------------------------------------------------
extern "C" void kernel_launch(void* const* d_in, const int* in_sizes, int n_in,
                              void* d_out, int out_size) {
    const float* x    = (const float*)d_in[0];
    const float* nw   = (const float*)d_in[1];
    const float* nb   = (const float*)d_in[2];
    const float* qkvw = (const float*)d_in[3];
    const float* qkvb = (const float*)d_in[4];
    const float* pw   = (const float*)d_in[5];
    const float* pb   = (const float*)d_in[6];
    float* out = (float*)d_out;

    __half *hT, *qkT, *v, *ath, *oT, *wq, *wp;
    float* attn;
    cudaGetSymbolAddress((void**)&hT, g_hT);
    cudaGetSymbolAddress((void**)&qkT, g_qkT);
    cudaGetSymbolAddress((void**)&v, g_v);
    cudaGetSymbolAddress((void**)&attn, g_attn);
    cudaGetSymbolAddress((void**)&ath, g_attn_h);
    cudaGetSymbolAddress((void**)&oT, g_oT);
    cudaGetSymbolAddress((void**)&wq, g_wqkv);
    cudaGetSymbolAddress((void**)&wp, g_wp);

    cudaFuncSetAttribute(qkv_combo,  cudaFuncAttributeMaxDynamicSharedMemorySize, SMEM_BYTES);
    cudaFuncSetAttribute(mma_gemm<2>, cudaFuncAttributeMaxDynamicSharedMemorySize, SMEM_BYTES);
    cudaFuncSetAttribute(mma_gemm<3>, cudaFuncAttributeMaxDynamicSharedMemorySize, SMEM_BYTES);
    cudaFuncSetAttribute(mma_gemm<4>, cudaFuncAttributeMaxDynamicSharedMemorySize, SMEM_BYTES);

    const long long sHT = (long long)NSP * CHN;
    const long long sQK = (long long)NSP * 1024;
    const long long sV  = (long long)CHN * NSP;
    const long long sAT = (long long)NSP * NSP;
    const float scale = 0.044194173824159216f;  // 512^-0.5

    cast_h<<<768, 256>>>(qkvw, wq, 3 * CHN * CHN);
    cast_h<<<256, 256>>>(pw, wp, CHN * CHN);

    // 1) GroupNorm -> hT fp16  [B, N, C]
    groupnorm_t<<<NB * 8, 256>>>(x, nw, nb, hT);

    // 2+3) QK and V in one launch (independent given hT)
    qkv_combo<<<dim3(8, 12, NB), 256, SMEM_BYTES>>>(hT, wq, qkT, v, qkvb);

    // 4) attn[i, j] = scale * sum_c qT[i,c] * kT[j,c]   (fp32 out)
    mma_gemm<2><<<dim3(NSP / NT, NSP / MT, NB), 256, SMEM_BYTES>>>(
        qkT, 1024, sQK, qkT + CHN, 1024, sQK, CHN,
        attn, nullptr, NSP, sAT, nullptr, nullptr, 0LL, scale);

    // 5) softmax -> probs fp16
    softmax_h<<<NB * NSP, 256>>>(attn, ath);

    // 6) oT[i, c] = sum_j attn[i,j] * v[c,j]
    mma_gemm<3><<<dim3(CHN / NT, NSP / MT, NB), 256, SMEM_BYTES>>>(
        ath, NSP, sAT, v, NSP, sV, NSP,
        nullptr, oT, CHN, sHT, nullptr, nullptr, 0LL, 1.f);

    // 7) out[o, n] = sum_c P[o,c] * oT[n,c] + pb[o] + x[b,o,n]
    mma_gemm<4><<<dim3(NSP / NT, CHN / MT, NB), 256, SMEM_BYTES>>>(
        wp, CHN, 0LL, oT, CHN, sHT, CHN,
        out, nullptr, NSP, sV, pb, x, sV, 1.f);
}

// round 16
// speedup vs baseline: 1.0896x; 1.0896x over previous
#include <cuda_runtime.h>
#include <cuda_fp16.h>

#define NB   16
#define CHN  512
#define NSP  1024

// Scratch (__device__ globals — allocation-rule safe). Pure fp16.
__device__ __half g_hT[(size_t)NB * NSP * CHN];         // groupnorm out, [B,N,C]
__device__ __half g_qkT[(size_t)NB * NSP * 2 * CHN];    // q|k, [B,N,2C]
__device__ __half g_v[(size_t)NB * CHN * NSP];          // v, [B,C,N]
__device__ __half g_attn_h[(size_t)NB * NSP * NSP];     // scores/probs fp16 (in-place)
__device__ __half g_oT[(size_t)NB * NSP * CHN];         // attn@v, [B,N,C]
__device__ __half g_wqkv[3 * CHN * CHN];
__device__ __half g_wp[CHN * CHN];

// ---------------- helpers ----------------
__device__ __forceinline__ unsigned smem_u32(const void* p) {
    unsigned a;
    asm("{ .reg .u64 t; cvta.to.shared.u64 t, %1; cvt.u32.u64 %0, t; }"
        : "=r"(a) : "l"(p));
    return a;
}
__device__ __forceinline__ void ldsm4(unsigned r[4], unsigned addr) {
    asm volatile("ldmatrix.sync.aligned.m8n8.x4.shared.b16 {%0,%1,%2,%3}, [%4];"
                 : "=r"(r[0]), "=r"(r[1]), "=r"(r[2]), "=r"(r[3]) : "r"(addr));
}
__device__ __forceinline__ void mma16816(float c[4], const unsigned a[4], const unsigned b[2]) {
    asm volatile(
        "mma.sync.aligned.m16n8k16.row.col.f32.f16.f16.f32 "
        "{%0,%1,%2,%3}, {%4,%5,%6,%7}, {%8,%9}, {%0,%1,%2,%3};"
        : "+f"(c[0]), "+f"(c[1]), "+f"(c[2]), "+f"(c[3])
        : "r"(a[0]), "r"(a[1]), "r"(a[2]), "r"(a[3]), "r"(b[0]), "r"(b[1]));
}
__device__ __forceinline__ void cpa16(unsigned dst, const void* src) {
    asm volatile("cp.async.cg.shared.global [%0], [%1], 16;" :: "r"(dst), "l"(src));
}
#define CPA_COMMIT() asm volatile("cp.async.commit_group;" ::: "memory")
#define CPA_WAIT(n)  asm volatile("cp.async.wait_group %0;" :: "n"(n) : "memory")

// ---------------------------------------------------------------------------
// GEMM body: D[m,n] = sum_k A[m,k]*B[n,k] (K-major), fp16 -> fp32 accum.
// Block tile 128x128, KC=32, 2-stage cp.async, 2 CTAs/SM. Warp tile 64x32.
// Hoisted ldsm4 batches per ks-step, 16-MMA bursts. (R14 core, unchanged.)
// EPI: 0 QK(+bias[n], fp16) | 1 V(+bias[m], fp16) | 3 AV(fp16)
//      4 PROJ(+bias[m]+resid, f32) | 5 SCORE(*alpha, fp16)
// ---------------------------------------------------------------------------
#define MT 128
#define NT 128
#define KC 32
#define PITCH 80                 // bytes per smem row (conflict-free ldmatrix)
#define TILE_B (128 * PITCH)     // 10240
#define OFF_A  0
#define OFF_B  TILE_B
#define STAGE  (2 * TILE_B)      // 20480
#define SMEM_BYTES (2 * STAGE)   // 40960

template <int EPI>
__device__ __forceinline__ void gemm_body(
    int bx, int by, int bz, char* smem,
    const __half* __restrict__ Ah, int lda, long long sA,
    const __half* __restrict__ Bh, int ldb, long long sB, int K,
    float* __restrict__ Cf, __half* __restrict__ Ch,
    int ldc, long long sC,
    const float* __restrict__ bias,
    const float* __restrict__ resid, long long sR, float alpha) {
    const unsigned sb = smem_u32(smem);
    const int tid = threadIdx.x, lane = tid & 31, wid = tid >> 5;
    const int m0 = by * MT, n0 = bx * NT;
    const int wm0 = (wid >> 2) * 64, wn0 = (wid & 3) * 32;

    const int grow = tid >> 1;
    const int gsegB = (tid & 1) * 32;

    const char* pA = (const char*)(Ah + (size_t)bz * sA + (size_t)(m0 + grow) * lda) + gsegB;
    const char* pB = (const char*)(Bh + (size_t)bz * sB + (size_t)(n0 + grow) * ldb) + gsegB;
    const unsigned drow = (unsigned)(grow * PITCH + gsegB);

    const unsigned aLane = (unsigned)((wm0 + (lane & 15)) * PITCH + ((lane >> 4) & 1) * 16);
    const unsigned bLane = (unsigned)((wn0 + (lane & 7) + ((lane >> 4) & 1) * 8) * PITCH
                                      + ((lane >> 3) & 1) * 16);

    auto fill = [&](int c) {
        const unsigned d = sb + (unsigned)((c & 1) * STAGE) + drow;
        const size_t kb = (size_t)c * (KC * 2);
        cpa16(d + OFF_A, pA + kb); cpa16(d + OFF_A + 16, pA + kb + 16);
        cpa16(d + OFF_B, pB + kb); cpa16(d + OFF_B + 16, pB + kb + 16);
        CPA_COMMIT();
    };

    const int nch = K / KC;
    fill(0);

    float acc[4][4][4] = {};

    for (int c = 0; c < nch; c++) {
        CPA_WAIT(0);
        __syncthreads();
        if (c + 1 < nch) fill(c + 1);

        const unsigned sbuf = sb + (unsigned)((c & 1) * STAGE);
#pragma unroll
        for (int ks = 0; ks < 2; ks++) {
            unsigned bf[4][2];
            {
                unsigned t[4];
                ldsm4(t, sbuf + OFF_B + bLane + ks * 32);
                bf[0][0] = t[0]; bf[0][1] = t[1];
                bf[1][0] = t[2]; bf[1][1] = t[3];
                ldsm4(t, sbuf + OFF_B + bLane + 16 * PITCH + ks * 32);
                bf[2][0] = t[0]; bf[2][1] = t[1];
                bf[3][0] = t[2]; bf[3][1] = t[3];
            }
            unsigned af[4][4];
#pragma unroll
            for (int am = 0; am < 4; am++)
                ldsm4(af[am], sbuf + OFF_A + aLane + am * (16 * PITCH) + ks * 32);
#pragma unroll
            for (int am = 0; am < 4; am++)
#pragma unroll
                for (int an = 0; an < 4; an++)
                    mma16816(acc[am][an], af[am], bf[an]);
        }
    }

    // ---- epilogue ----
    const int r0 = m0 + wm0 + (lane >> 2);
    const int c0 = n0 + wn0 + (lane & 3) * 2;
#pragma unroll
    for (int am = 0; am < 4; am++) {
#pragma unroll
        for (int an = 0; an < 4; an++) {
            float f0 = acc[am][an][0], f1 = acc[am][an][1];
            float f2 = acc[am][an][2], f3 = acc[am][an][3];
            const int r = r0 + am * 16;
            const int cc = c0 + an * 8;
            if (EPI == 5) { f0 *= alpha; f1 *= alpha; f2 *= alpha; f3 *= alpha; }
            if (EPI == 0) {
                float b0 = bias[cc], b1 = bias[cc + 1];
                f0 += b0; f1 += b1; f2 += b0; f3 += b1;
            }
            if (EPI == 1 || EPI == 4) {
                float ba = bias[r], bb = bias[r + 8];
                f0 += ba; f1 += ba; f2 += bb; f3 += bb;
            }
            const size_t o0 = (size_t)bz * sC + (size_t)r * ldc + cc;
            const size_t o1 = o0 + (size_t)8 * ldc;
            if (EPI == 4) {
                const float* rp = resid + (size_t)bz * sR + (size_t)r * ldc + cc;
                float2 rv0 = *(const float2*)rp;
                float2 rv1 = *(const float2*)(rp + (size_t)8 * ldc);
                f0 += rv0.x; f1 += rv0.y; f2 += rv1.x; f3 += rv1.y;
                *(float2*)(Cf + o0) = make_float2(f0, f1);
                *(float2*)(Cf + o1) = make_float2(f2, f3);
            } else {
                union { __half b[2]; unsigned u; } H0, H1;
                H0.b[0] = __float2half_rn(f0); H0.b[1] = __float2half_rn(f1);
                H1.b[0] = __float2half_rn(f2); H1.b[1] = __float2half_rn(f3);
                *(unsigned*)(Ch + o0) = H0.u;
                *(unsigned*)(Ch + o1) = H1.u;
            }
        }
    }
}

template <int EPI>
__global__ void __launch_bounds__(256, 2) mma_gemm(
    const __half* __restrict__ Ah, int lda, long long sA,
    const __half* __restrict__ Bh, int ldb, long long sB, int K,
    float* __restrict__ Cf, __half* __restrict__ Ch,
    int ldc, long long sC,
    const float* __restrict__ bias,
    const float* __restrict__ resid, long long sR, float alpha) {
    extern __shared__ char smem[];
    gemm_body<EPI>(blockIdx.x, blockIdx.y, blockIdx.z, smem,
                   Ah, lda, sA, Bh, ldb, sB, K, Cf, Ch, ldc, sC,
                   bias, resid, sR, alpha);
}

// Combined SCORES + V kernel — both runnable once qkT (scores) / hT (v) exist.
// grid (8, 12, 16): y<8 -> scores tile, y>=8 -> V tile (by-8 in [0,4)).
__global__ void __launch_bounds__(256, 2) sv_combo(
    const __half* __restrict__ qkT, const __half* __restrict__ hT,
    const __half* __restrict__ wq,
    __half* __restrict__ ath, __half* __restrict__ v,
    const float* __restrict__ qkvb, float alpha) {
    extern __shared__ char smem[];
    const long long sHT = (long long)NSP * CHN;
    const long long sQK = (long long)NSP * 1024;
    const long long sV  = (long long)CHN * NSP;
    const long long sAT = (long long)NSP * NSP;
    if (blockIdx.y < 8) {
        // attn[i, j] = alpha * sum_c qT[i,c] * kT[j,c]  (fp16 out)
        gemm_body<5>(blockIdx.x, blockIdx.y, blockIdx.z, smem,
                     qkT, 1024, sQK, qkT + CHN, 1024, sQK, CHN,
                     nullptr, ath, NSP, sAT, nullptr, nullptr, 0LL, alpha);
    } else {
        // v[c, n] = sum_k Wv[c,k] * hT[n,k] + qkv_b[1024+c]
        gemm_body<1>(blockIdx.x, blockIdx.y - 8, blockIdx.z, smem,
                     wq + 1024 * CHN, CHN, 0LL, hT, CHN, sHT, CHN,
                     nullptr, v, NSP, sV, qkvb + 1024, nullptr, 0LL, 1.f);
    }
}

// ---------------------------------------------------------------------------
// GroupNorm -> transposed fp16 output hT[B, N, C]
// ---------------------------------------------------------------------------
__global__ void __launch_bounds__(256) groupnorm_t(const float* __restrict__ x,
                                                   const float* __restrict__ gw,
                                                   const float* __restrict__ gb,
                                                   __half* __restrict__ hh) {
    const int b = blockIdx.x >> 3, g = blockIdx.x & 7;
    const float* xp = x + ((size_t)b * CHN + (size_t)g * 64) * NSP;

    float s = 0.f, ss = 0.f;
    for (int i = threadIdx.x * 4; i < 64 * NSP; i += 1024) {
        float4 v = *(const float4*)(xp + i);
        s += v.x + v.y + v.z + v.w;
        ss += v.x * v.x + v.y * v.y + v.z * v.z + v.w * v.w;
    }
    __shared__ float sa[8], sb2[8];
    for (int o = 16; o > 0; o >>= 1) {
        s += __shfl_xor_sync(0xffffffffu, s, o);
        ss += __shfl_xor_sync(0xffffffffu, ss, o);
    }
    if ((threadIdx.x & 31) == 0) { sa[threadIdx.x >> 5] = s; sb2[threadIdx.x >> 5] = ss; }
    __syncthreads();
    s = 0.f; ss = 0.f;
#pragma unroll
    for (int i = 0; i < 8; i++) { s += sa[i]; ss += sb2[i]; }
    const float inv_n = 1.f / (64.f * (float)NSP);
    const float mean = s * inv_n;
    const float rstd = rsqrtf(ss * inv_n - mean * mean + 1e-5f);

    const int ci_w = threadIdx.x & 63;
    const int cg = g * 64 + ci_w;
    const float sc = gw[cg] * rstd;
    const float bi = gb[cg] - mean * sc;

    __shared__ float tile[64][65];
    const int ci_r = threadIdx.x >> 2;
    const int nj = (threadIdx.x & 3) * 16;
    const int nbase = (threadIdx.x >> 6) * 16;

    for (int tt = 0; tt < 16; tt++) {
        const int n0 = tt * 64;
        __syncthreads();
        const float* src = xp + (size_t)ci_r * NSP + n0 + nj;
#pragma unroll
        for (int q = 0; q < 4; q++) {
            float4 v = *(const float4*)(src + q * 4);
            tile[ci_r][nj + q*4 + 0] = v.x; tile[ci_r][nj + q*4 + 1] = v.y;
            tile[ci_r][nj + q*4 + 2] = v.z; tile[ci_r][nj + q*4 + 3] = v.w;
        }
        __syncthreads();
#pragma unroll
        for (int k = 0; k < 16; k++) {
            const int nl = nbase + k;
            float y = tile[ci_w][nl] * sc + bi;
            hh[((size_t)b * NSP + n0 + nl) * CHN + cg] = __float2half_rn(y);
        }
    }
}

// ---------------------------------------------------------------------------
// Softmax in-place on fp16 scores -> fp16 probs
// ---------------------------------------------------------------------------
__global__ void __launch_bounds__(256) softmax_h2(__half* __restrict__ a) {
    __shared__ float red[8];
    __half* row = a + (size_t)blockIdx.x * NSP;
    uint2 raw = ((const uint2*)row)[threadIdx.x];
    __half2 h0 = *(__half2*)&raw.x, h1 = *(__half2*)&raw.y;
    float2 f0 = __half22float2(h0), f1 = __half22float2(h1);
    float vx = f0.x, vy = f0.y, vz = f1.x, vw = f1.y;

    float m = fmaxf(fmaxf(vx, vy), fmaxf(vz, vw));
    for (int o = 16; o > 0; o >>= 1) m = fmaxf(m, __shfl_xor_sync(0xffffffffu, m, o));
    int w = threadIdx.x >> 5;
    if ((threadIdx.x & 31) == 0) red[w] = m;
    __syncthreads();
    m = red[0];
#pragma unroll
    for (int i = 1; i < 8; i++) m = fmaxf(m, red[i]);

    vx = __expf(vx - m); vy = __expf(vy - m);
    vz = __expf(vz - m); vw = __expf(vw - m);
    float su = vx + vy + vz + vw;
    for (int o = 16; o > 0; o >>= 1) su += __shfl_xor_sync(0xffffffffu, su, o);
    __syncthreads();
    if ((threadIdx.x & 31) == 0) red[w] = su;
    __syncthreads();
    su = red[0] + red[1] + red[2] + red[3] + red[4] + red[5] + red[6] + red[7];
    float inv = 1.0f / su;

    union { __half b[4]; uint2 u; } P;
    P.b[0] = __float2half_rn(vx * inv);
    P.b[1] = __float2half_rn(vy * inv);
    P.b[2] = __float2half_rn(vz * inv);
    P.b[3] = __float2half_rn(vw * inv);
    ((uint2*)row)[threadIdx.x] = P.u;
}

// fp32 -> fp16
__global__ void cast_h(const float* __restrict__ s, __half* __restrict__ h, int n) {
    int i = (blockIdx.x * blockDim.x + threadIdx.x) * 4;
    if (i < n) {
        float4 v = *(const float4*)(s + i);
        union { __half b[4]; uint2 u; } P;
        P.b[0] = __float2half_rn(v.x); P.b[1] = __float2half_rn(v.y);
        P.b[2] = __float2half_rn(v.z); P.b[3] = __float2half_rn(v.w);
        *(uint2*)(h + i) = P.u;
    }
}

// ---------------------------------------------------------------------------
extern "C" void kernel_launch(void* const* d_in, const int* in_sizes, int n_in,
                              void* d_out, int out_size) {
    const float* x    = (const float*)d_in[0];
    const float* nw   = (const float*)d_in[1];
    const float* nb   = (const float*)d_in[2];
    const float* qkvw = (const float*)d_in[3];
    const float* qkvb = (const float*)d_in[4];
    const float* pw   = (const float*)d_in[5];
    const float* pb   = (const float*)d_in[6];
    float* out = (float*)d_out;

    __half *hT, *qkT, *v, *ath, *oT, *wq, *wp;
    cudaGetSymbolAddress((void**)&hT, g_hT);
    cudaGetSymbolAddress((void**)&qkT, g_qkT);
    cudaGetSymbolAddress((void**)&v, g_v);
    cudaGetSymbolAddress((void**)&ath, g_attn_h);
    cudaGetSymbolAddress((void**)&oT, g_oT);
    cudaGetSymbolAddress((void**)&wq, g_wqkv);
    cudaGetSymbolAddress((void**)&wp, g_wp);

    const long long sHT = (long long)NSP * CHN;
    const long long sQK = (long long)NSP * 1024;
    const long long sV  = (long long)CHN * NSP;
    const long long sAT = (long long)NSP * NSP;
    const float scale = 0.044194173824159216f;  // 512^-0.5

    cast_h<<<768, 256>>>(qkvw, wq, 3 * CHN * CHN);
    cast_h<<<256, 256>>>(pw, wp, CHN * CHN);

    // 1) GroupNorm -> hT fp16  [B, N, C]
    groupnorm_t<<<NB * 8, 256>>>(x, nw, nb, hT);

    // 2) qkT[n, o] = sum_c hT[n,c] * Wqk[o,c] + qkv_b[o]
    mma_gemm<0><<<dim3(1024 / NT, NSP / MT, NB), 256, SMEM_BYTES>>>(
        hT, CHN, sHT, wq, CHN, 0LL, CHN,
        nullptr, qkT, 1024, sQK, qkvb, nullptr, 0LL, 1.f);

    // 3+4) scores (fp16, scaled) and v in one launch
    sv_combo<<<dim3(8, 12, NB), 256, SMEM_BYTES>>>(qkT, hT, wq, ath, v, qkvb, scale);

    // 5) softmax in-place on fp16 scores
    softmax_h2<<<NB * NSP, 256>>>(ath);

    // 6) oT[i, c] = sum_j attn[i,j] * v[c,j]
    mma_gemm<3><<<dim3(CHN / NT, NSP / MT, NB), 256, SMEM_BYTES>>>(
        ath, NSP, sAT, v, NSP, sV, NSP,
        nullptr, oT, CHN, sHT, nullptr, nullptr, 0LL, 1.f);

    // 7) out[o, n] = sum_c P[o,c] * oT[n,c] + pb[o] + x[b,o,n]
    mma_gemm<4><<<dim3(NSP / NT, CHN / MT, NB), 256, SMEM_BYTES>>>(
        wp, CHN, 0LL, oT, CHN, sHT, CHN,
        out, nullptr, NSP, sV, pb, x, sV, 1.f);
}